// round 3
// baseline (speedup 1.0000x reference)
#include <cuda_runtime.h>

// AttentionAggregator: out[n] = sum_k softmax_k(feats[n,k]·w) * feats[n,k],
// feats[n,k] = embed_table[neigh_idx[n,k]].
// table [VOCAB,128] f32, attn_w [128] f32, neigh_idx [N,10] (int32 OR int64), out [N,128] f32.

#define K_NEIGH 10

__device__ int g_idx_is64;   // 1 if neigh_idx buffer is int64, 0 if int32

// Detect index dtype: view buffer as int32 words. For little-endian int64
// indices in [0, 2^31), every odd word is 0. For an int32 index buffer the
// odd-position words are random values in [0, VOCAB) — essentially never all 0.
__global__ void detect_idx_dtype_kernel(const int* __restrict__ idx_words, int n_words)
{
    __shared__ int nz;
    if (threadIdx.x == 0) nz = 0;
    __syncthreads();
    int local = 0;
    for (int i = threadIdx.x; i < n_words / 2; i += blockDim.x) {
        if (idx_words[2 * i + 1] != 0) local = 1;
    }
    if (local) atomicOr(&nz, 1);
    __syncthreads();
    if (threadIdx.x == 0) g_idx_is64 = (nz == 0) ? 1 : 0;
}

__global__ __launch_bounds__(256) void attn_agg_kernel(
    const float* __restrict__ table,
    const float* __restrict__ attn_w,
    const void* __restrict__ neigh_idx,
    float* __restrict__ out,
    int n_nodes,
    int vocab)
{
    int gwarp = (int)((blockIdx.x * (unsigned)blockDim.x + threadIdx.x) >> 5);
    int lane  = threadIdx.x & 31;
    if (gwarp >= n_nodes) return;

    const int is64 = g_idx_is64;          // uniform across grid
    const float4* __restrict__ tbl4 = (const float4*)table;
    float4 w4 = ((const float4*)attn_w)[lane];

    float4 f[K_NEIGH];
    float  s[K_NEIGH];

    // Gather all K rows (each row: 32 lanes x float4 = 512B coalesced) and
    // per-lane partial dot products. Loads independent -> MLP=10.
    #pragma unroll
    for (int k = 0; k < K_NEIGH; k++) {
        long long r;
        if (is64) r = ((const long long*)neigh_idx)[(size_t)gwarp * K_NEIGH + k];
        else      r = (long long)((const int*)neigh_idx)[(size_t)gwarp * K_NEIGH + k];
        // clamp (indices are in range; this is a crash guard only)
        r = r < 0 ? 0 : (r >= vocab ? vocab - 1 : r);
        f[k] = tbl4[(size_t)r * 32 + lane];
        s[k] = f[k].x * w4.x + f[k].y * w4.y + f[k].z * w4.z + f[k].w * w4.w;
    }

    // Batched warp reduction: all 10 scores reduced in 5 shuffle rounds.
    #pragma unroll
    for (int off = 16; off > 0; off >>= 1) {
        #pragma unroll
        for (int k = 0; k < K_NEIGH; k++)
            s[k] += __shfl_xor_sync(0xffffffffu, s[k], off);
    }

    // Softmax over K (every lane now holds the full 10-score vector).
    float m = s[0];
    #pragma unroll
    for (int k = 1; k < K_NEIGH; k++) m = fmaxf(m, s[k]);

    float sum = 0.0f;
    #pragma unroll
    for (int k = 0; k < K_NEIGH; k++) {
        s[k] = __expf(s[k] - m);
        sum += s[k];
    }
    float inv = __frcp_rn(sum);

    float4 acc = make_float4(0.f, 0.f, 0.f, 0.f);
    #pragma unroll
    for (int k = 0; k < K_NEIGH; k++) {
        float wk = s[k] * inv;
        acc.x = fmaf(wk, f[k].x, acc.x);
        acc.y = fmaf(wk, f[k].y, acc.y);
        acc.z = fmaf(wk, f[k].z, acc.z);
        acc.w = fmaf(wk, f[k].w, acc.w);
    }

    ((float4*)out)[(size_t)gwarp * 32 + lane] = acc;
}

extern "C" void kernel_launch(void* const* d_in, const int* in_sizes, int n_in,
                              void* d_out, int out_size)
{
    // Identify inputs by element count, not position:
    //   attn_w: exactly 128 elements
    //   table:  large, multiple of 128 (VOCAB*128)
    //   idx:    the remaining one (N*10 elements)
    int ti = -1, wi = -1, ii = -1;
    for (int i = 0; i < n_in; i++) {
        if (in_sizes[i] == 128 && wi < 0) { wi = i; continue; }
        if (in_sizes[i] >= (1 << 20) && (in_sizes[i] % 128) == 0 && ti < 0) { ti = i; continue; }
    }
    for (int i = 0; i < n_in; i++) if (i != ti && i != wi) { ii = i; break; }

    const float* table  = (const float*)d_in[ti];
    const float* attn_w = (const float*)d_in[wi];
    const void*  nidx   = d_in[ii];

    int n_idx_elems = in_sizes[ii];
    int n_nodes = n_idx_elems / K_NEIGH;
    int vocab   = in_sizes[ti] / 128;

    // Pass 1: detect whether the index buffer is int32 or int64. Scans only the
    // first 2048 int32 words, which exist under either dtype.
    int n_words = n_idx_elems < 2048 ? n_idx_elems : 2048;
    detect_idx_dtype_kernel<<<1, 256>>>((const int*)nidx, n_words);

    // Pass 2: main kernel. 8 warps (8 nodes) per 256-thread block.
    int blocks = (n_nodes + 7) / 8;
    attn_agg_kernel<<<blocks, 256>>>(table, attn_w, nidx, (float*)d_out, n_nodes, vocab);
}